// round 14
// baseline (speedup 1.0000x reference)
#include <cuda_runtime.h>
#include <cuda_bf16.h>
#include <cstdint>

#define B_ 2
#define T_ 2048
#define H_ 16
#define D_ 64
#define C_ 1024

// ---------------- scratch (no cudaMalloc allowed) ----------------
__device__ float g_q[(size_t)B_ * H_ * T_ * D_];       // [B,H,T,D]
__device__ float g_k[(size_t)B_ * H_ * T_ * D_];
__device__ float g_v[(size_t)B_ * H_ * T_ * D_];
__device__ float g_y[(size_t)B_ * T_ * C_];            // attention out [B,T,C]
__device__ float g_W[H_ * T_];                          // mask weight table [H][rel]
__device__ int   g_bad[2];                              // [0]=qkv, [1]=proj

// bf16 split-precision buffers
__device__ __nv_bfloat16 g_xhi[(size_t)4096 * 1024];
__device__ __nv_bfloat16 g_xlo[(size_t)4096 * 1024];
__device__ __nv_bfloat16 g_yhi[(size_t)4096 * 1024];
__device__ __nv_bfloat16 g_ylo[(size_t)4096 * 1024];
__device__ __nv_bfloat16 g_wahiT[(size_t)3072 * 1024];  // w_attn^T [N,K]
__device__ __nv_bfloat16 g_waloT[(size_t)3072 * 1024];
__device__ __nv_bfloat16 g_wphiT[(size_t)1024 * 1024];  // w_proj^T [N,K]
__device__ __nv_bfloat16 g_wploT[(size_t)1024 * 1024];

// ---------------- packed f32x2 helpers ----------------
typedef unsigned long long ull;

__device__ __forceinline__ ull dup2(float x) {
    ull r;
    asm("mov.b64 %0, {%1, %1};" : "=l"(r) : "f"(x));
    return r;
}
__device__ __forceinline__ void fma2(ull& d, ull a, ull b) {
    asm("fma.rn.f32x2 %0, %1, %2, %0;" : "+l"(d) : "l"(a), "l"(b));
}
__device__ __forceinline__ void mul2(ull& d, ull a, ull b) {
    asm("mul.rn.f32x2 %0, %1, %2;" : "=l"(d) : "l"(a), "l"(b));
}
__device__ __forceinline__ float2 unpack2(ull v) {
    float2 f;
    f.x = __uint_as_float((unsigned)v);
    f.y = __uint_as_float((unsigned)(v >> 32));
    return f;
}
__device__ __forceinline__ int sw4(int major) { return ((major >> 2) & 7) << 2; }

__device__ __forceinline__ uint32_t smem_u32(const void* p) {
    uint32_t a;
    asm("{ .reg .u64 t; cvta.to.shared.u64 t, %1; cvt.u32.u64 %0, t; }" : "=r"(a) : "l"(p));
    return a;
}

// ---------------- warp-level MMA primitives (base PTX, sm_80+) ----------------
__device__ __forceinline__ void mma16816(float* c, const unsigned* a, const unsigned* b) {
    asm volatile("mma.sync.aligned.m16n8k16.row.col.f32.bf16.bf16.f32 "
                 "{%0,%1,%2,%3}, {%4,%5,%6,%7}, {%8,%9}, {%0,%1,%2,%3};"
                 : "+f"(c[0]), "+f"(c[1]), "+f"(c[2]), "+f"(c[3])
                 : "r"(a[0]), "r"(a[1]), "r"(a[2]), "r"(a[3]), "r"(b[0]), "r"(b[1]));
}
__device__ __forceinline__ void ldsm4(unsigned* r, uint32_t addr) {
    asm volatile("ldmatrix.sync.aligned.m8n8.x4.shared.b16 {%0,%1,%2,%3}, [%4];"
                 : "=r"(r[0]), "=r"(r[1]), "=r"(r[2]), "=r"(r[3]) : "r"(addr));
}
__device__ __forceinline__ void ldsm2(unsigned* r, uint32_t addr) {
    asm volatile("ldmatrix.sync.aligned.m8n8.x2.shared.b16 {%0,%1}, [%2];"
                 : "=r"(r[0]), "=r"(r[1]) : "r"(addr));
}

// ---------------- flag reset ----------------
__global__ void reset_flags_kernel() { g_bad[0] = 0; g_bad[1] = 0; }

// ---------------- split / split+transpose conversion kernels ----------------
__global__ __launch_bounds__(256)
void split_kernel(const float* __restrict__ src, __nv_bfloat16* __restrict__ hi,
                  __nv_bfloat16* __restrict__ lo) {
    int i = blockIdx.x * 256 + threadIdx.x;          // float4 index
    float4 v = ((const float4*)src)[i];
    __nv_bfloat16 h0 = __float2bfloat16(v.x), h1 = __float2bfloat16(v.y);
    __nv_bfloat16 h2 = __float2bfloat16(v.z), h3 = __float2bfloat16(v.w);
    __nv_bfloat16 l0 = __float2bfloat16(v.x - __bfloat162float(h0));
    __nv_bfloat16 l1 = __float2bfloat16(v.y - __bfloat162float(h1));
    __nv_bfloat16 l2 = __float2bfloat16(v.z - __bfloat162float(h2));
    __nv_bfloat16 l3 = __float2bfloat16(v.w - __bfloat162float(h3));
    ((__nv_bfloat162*)hi)[2 * i + 0] = __halves2bfloat162(h0, h1);
    ((__nv_bfloat162*)hi)[2 * i + 1] = __halves2bfloat162(h2, h3);
    ((__nv_bfloat162*)lo)[2 * i + 0] = __halves2bfloat162(l0, l1);
    ((__nv_bfloat162*)lo)[2 * i + 1] = __halves2bfloat162(l2, l3);
}

// W [K=1024, N] row-major -> hiT/loT [N, 1024] (K contiguous)
__global__ __launch_bounds__(256)
void splitT_kernel(const float* __restrict__ Wm, __nv_bfloat16* __restrict__ hiT,
                   __nv_bfloat16* __restrict__ loT, int N) {
    __shared__ float t[32][33];
    const int n0 = blockIdx.x * 32, k0 = blockIdx.y * 32;
    const int tx = threadIdx.x & 31, ty = threadIdx.x >> 5;   // 32 x 8
#pragma unroll
    for (int i = 0; i < 4; i++)
        t[ty + 8 * i][tx] = Wm[(size_t)(k0 + ty + 8 * i) * N + n0 + tx];
    __syncthreads();
#pragma unroll
    for (int i = 0; i < 4; i++) {
        int n = n0 + ty + 8 * i, k = k0 + tx;
        float v = t[tx][ty + 8 * i];
        __nv_bfloat16 h = __float2bfloat16(v);
        __nv_bfloat16 l = __float2bfloat16(v - __bfloat162float(h));
        hiT[(size_t)n * 1024 + k] = h;
        loT[(size_t)n * 1024 + k] = l;
    }
}

// ---------------- tensor-core GEMM via mma.sync (bf16 split, 3 terms) ----------
// Tile 128x128, Kc=64, 8 warps in 2(m) x 4(n): each warp 64x32 = 4x4 m16n8k16.
#define LDS_ 72   // bf16 per smem row (64 + 8 pad -> ldmatrix conflict-free)

__device__ __forceinline__ void load_tile_mma(__nv_bfloat16* dst, const __nv_bfloat16* src,
                                              int row0, int k0, int tid) {
#pragma unroll
    for (int it = 0; it < 4; it++) {
        int idx = it * 256 + tid;
        int row = idx >> 3, seg = idx & 7;
        *(uint4*)(dst + row * LDS_ + seg * 8) =
            *(const uint4*)(src + (size_t)(row0 + row) * 1024 + k0 + seg * 8);
    }
}

template<bool QKV>
__global__ __launch_bounds__(256)
void mma_gemm_kernel(const float* __restrict__ bias, float* __restrict__ C) {
    const int N = QKV ? 3072 : 1024;
    const __nv_bfloat16* Ahi = QKV ? g_xhi : g_yhi;
    const __nv_bfloat16* Alo = QKV ? g_xlo : g_ylo;
    const __nv_bfloat16* Bhi = QKV ? g_wahiT : g_wphiT;
    const __nv_bfloat16* Blo = QKV ? g_waloT : g_wploT;

    extern __shared__ __nv_bfloat16 sm[];
    __nv_bfloat16* sAhi = sm;
    __nv_bfloat16* sAlo = sm + 128 * LDS_;
    __nv_bfloat16* sBhi = sm + 2 * 128 * LDS_;
    __nv_bfloat16* sBlo = sm + 3 * 128 * LDS_;
    const uint32_t uAhi = smem_u32(sAhi), uAlo = smem_u32(sAlo);
    const uint32_t uBhi = smem_u32(sBhi), uBlo = smem_u32(sBlo);

    const int tid = threadIdx.x, wid = tid >> 5, lane = tid & 31;
    const int warp_m = wid & 1, warp_n = wid >> 1;     // 2 x 4
    const int bn = blockIdx.x * 128, bm = blockIdx.y * 128;

    // ldmatrix per-lane source coordinates
    const int lrA = lane & 15, lkA = (lane >> 4) << 3;         // x4: 16 rows, 2 k-halves
    const int lrB = lane & 7,  lkB = ((lane >> 3) & 1) << 3;   // x2: 8 rows, 2 k-halves

    float acc[4][4][4];
#pragma unroll
    for (int mi = 0; mi < 4; mi++)
#pragma unroll
        for (int nj = 0; nj < 4; nj++)
#pragma unroll
            for (int e = 0; e < 4; e++) acc[mi][nj][e] = 0.0f;

    for (int chunk = 0; chunk < 16; chunk++) {
        const int k0 = chunk * 64;
        __syncthreads();
        load_tile_mma(sAhi, Ahi, bm, k0, tid);
        load_tile_mma(sAlo, Alo, bm, k0, tid);
        load_tile_mma(sBhi, Bhi, bn, k0, tid);
        load_tile_mma(sBlo, Blo, bn, k0, tid);
        __syncthreads();

#pragma unroll
        for (int ks = 0; ks < 4; ks++) {
            const int kb = ks * 16;
            unsigned bh[4][2], bl[4][2];
#pragma unroll
            for (int nj = 0; nj < 4; nj++) {
                uint32_t off = (uint32_t)((warp_n * 32 + nj * 8 + lrB) * LDS_ + kb + lkB) * 2;
                ldsm2(bh[nj], uBhi + off);
                ldsm2(bl[nj], uBlo + off);
            }
            unsigned a[4][4];
#pragma unroll
            for (int mi = 0; mi < 4; mi++) {
                uint32_t off = (uint32_t)((warp_m * 64 + mi * 16 + lrA) * LDS_ + kb + lkA) * 2;
                ldsm4(a[mi], uAhi + off);
            }
#pragma unroll
            for (int mi = 0; mi < 4; mi++)
#pragma unroll
                for (int nj = 0; nj < 4; nj++) {
                    mma16816(acc[mi][nj], a[mi], bh[nj]);   // hi*hi
                    mma16816(acc[mi][nj], a[mi], bl[nj]);   // hi*lo
                }
#pragma unroll
            for (int mi = 0; mi < 4; mi++) {
                uint32_t off = (uint32_t)((warp_m * 64 + mi * 16 + lrA) * LDS_ + kb + lkA) * 2;
                ldsm4(a[mi], uAlo + off);
            }
#pragma unroll
            for (int mi = 0; mi < 4; mi++)
#pragma unroll
                for (int nj = 0; nj < 4; nj++)
                    mma16816(acc[mi][nj], a[mi], bh[nj]);   // lo*hi
        }
    }

    // epilogue: c0,c1 -> (row, col..col+1); c2,c3 -> (row+8, same cols)
    const int g = lane >> 2, tig = lane & 3;
#pragma unroll
    for (int mi = 0; mi < 4; mi++) {
        const int row = bm + warp_m * 64 + mi * 16 + g;
#pragma unroll
        for (int nj = 0; nj < 4; nj++) {
            const int col = bn + warp_n * 32 + nj * 8 + 2 * tig;
            const float b0 = __ldg(&bias[col]), b1 = __ldg(&bias[col + 1]);
            float2 v0 = make_float2(acc[mi][nj][0] + b0, acc[mi][nj][1] + b1);
            float2 v1 = make_float2(acc[mi][nj][2] + b0, acc[mi][nj][3] + b1);
            if (QKV) {
                const int wh = col >> 10, cc = col & 1023, h = cc >> 6, d = cc & 63;
                float* base = (wh == 0) ? g_q : ((wh == 1) ? g_k : g_v);
                const int b0q = row >> 11, t0 = row & 2047;
                const int b1q = (row + 8) >> 11, t1 = (row + 8) & 2047;
                *(float2*)&base[((size_t)((b0q * H_ + h) * T_ + t0)) * D_ + d] = v0;
                *(float2*)&base[((size_t)((b1q * H_ + h) * T_ + t1)) * D_ + d] = v1;
            } else {
                *(float2*)&C[(size_t)row * N + col] = v0;
                *(float2*)&C[(size_t)(row + 8) * N + col] = v1;
            }
        }
    }
}

// ---------------- sampled verification of MMA results ----------------
template<bool QKV>
__global__ __launch_bounds__(256)
void check_kernel(const float* __restrict__ A, const float* __restrict__ Wm,
                  const float* __restrict__ bias, const float* __restrict__ C) {
    const int N = QKV ? 3072 : 1024;
    int gtid = blockIdx.x * 256 + threadIdx.x;
    int m = (gtid * 131) & 4095;
    int n = (gtid * 769) % N;
    float ref = bias[n];
    const float* arow = A + (size_t)m * 1024;
    for (int k = 0; k < 1024; k++)
        ref += arow[k] * Wm[(size_t)k * N + n];
    float got;
    if (QKV) {
        const int wh = n >> 10, cc = n & 1023, h = cc >> 6, d = cc & 63;
        const float* base = (wh == 0) ? g_q : ((wh == 1) ? g_k : g_v);
        const int b = m >> 11, t = m & 2047;
        got = base[((size_t)((b * H_ + h) * T_ + t)) * D_ + d];
    } else {
        got = C[(size_t)m * 1024 + n];
    }
    float err = fabsf(got - ref) / (fabsf(ref) + 0.1f);
    if (err > 1e-2f) g_bad[QKV ? 0 : 1] = 1;
}

// ---------------- SIMT fallback GEMM (R6-proven; early-exits when MMA OK) ----
template<bool QKV>
__global__ __launch_bounds__(256, 2)
void fb_gemm_kernel(const float* __restrict__ A, const float* __restrict__ Bm,
                    const float* __restrict__ bias, float* __restrict__ C,
                    int M, int N, int K) {
    if (g_bad[QKV ? 0 : 1] == 0) return;
    __shared__ float As[2][8][132];
    __shared__ float Bs[2][8][128];
    const int tid = threadIdx.x;
    const int tx = tid & 15, ty = tid >> 4;
    const int bm = blockIdx.y * 128, bn = blockIdx.x * 128;
    const int arow = tid >> 1, acol = (tid & 1) * 4;
    const int brow = tid >> 5, bcol = (tid & 31) * 4;

    ull acc[8][4];
#pragma unroll
    for (int i = 0; i < 8; i++)
#pragma unroll
        for (int j = 0; j < 4; j++) acc[i][j] = 0ull;

    const float* aptr = A + (size_t)(bm + arow) * K + acol;
    const float* bptr = Bm + (size_t)brow * N + bn + bcol;

    float4 av = *(const float4*)(aptr);
    float4 bv = *(const float4*)(bptr);
    As[0][acol + 0][arow] = av.x;
    As[0][acol + 1][arow] = av.y;
    As[0][acol + 2][arow] = av.z;
    As[0][acol + 3][arow] = av.w;
    *(float4*)&Bs[0][brow][bcol] = bv;
    __syncthreads();

    int stage = 0;
    for (int k0 = 0; k0 < K; k0 += 8) {
        const bool hasNext = (k0 + 8) < K;
        if (hasNext) {
            av = *(const float4*)(aptr + k0 + 8);
            bv = *(const float4*)(bptr + (size_t)(k0 + 8) * N);
        }
#pragma unroll
        for (int kk = 0; kk < 8; kk++) {
            float a[8];
            *(float4*)&a[0] = *(const float4*)&As[stage][kk][8 * ty];
            *(float4*)&a[4] = *(const float4*)&As[stage][kk][8 * ty + 4];
            ull b2[4];
            ulonglong2 bl0 = *(const ulonglong2*)&Bs[stage][kk][4 * tx];
            ulonglong2 bl1 = *(const ulonglong2*)&Bs[stage][kk][64 + 4 * tx];
            b2[0] = bl0.x; b2[1] = bl0.y; b2[2] = bl1.x; b2[3] = bl1.y;
#pragma unroll
            for (int i = 0; i < 8; i++) {
                ull aa = dup2(a[i]);
#pragma unroll
                for (int j = 0; j < 4; j++) fma2(acc[i][j], aa, b2[j]);
            }
        }
        if (hasNext) {
            int ns = stage ^ 1;
            As[ns][acol + 0][arow] = av.x;
            As[ns][acol + 1][arow] = av.y;
            As[ns][acol + 2][arow] = av.z;
            As[ns][acol + 3][arow] = av.w;
            *(float4*)&Bs[ns][brow][bcol] = bv;
            __syncthreads();
            stage = ns;
        }
    }

    const int g0 = bn + 4 * tx;
    const int g1 = g0 + 64;
    float bvals[8];
#pragma unroll
    for (int j = 0; j < 4; j++) bvals[j] = __ldg(&bias[g0 + j]);
#pragma unroll
    for (int j = 0; j < 4; j++) bvals[4 + j] = __ldg(&bias[g1 + j]);

    if (QKV) {
        const int wh0 = g0 >> 10, cc0 = g0 & 1023, h0 = cc0 >> 6, d00 = cc0 & 63;
        const int wh1 = g1 >> 10, cc1 = g1 & 1023, h1 = cc1 >> 6, d01 = cc1 & 63;
        float* base0 = (wh0 == 0) ? g_q : ((wh0 == 1) ? g_k : g_v);
        float* base1 = (wh1 == 0) ? g_q : ((wh1 == 1) ? g_k : g_v);
#pragma unroll
        for (int i = 0; i < 8; i++) {
            int m = bm + 8 * ty + i;
            int b = m >> 11, t = m & 2047;
            float2 p0 = unpack2(acc[i][0]), p1 = unpack2(acc[i][1]);
            float2 p2 = unpack2(acc[i][2]), p3 = unpack2(acc[i][3]);
            float* r0 = base0 + ((size_t)((b * H_ + h0) * T_ + t)) * D_ + d00;
            float* r1 = base1 + ((size_t)((b * H_ + h1) * T_ + t)) * D_ + d01;
            *(float4*)r0 = make_float4(p0.x + bvals[0], p0.y + bvals[1],
                                       p1.x + bvals[2], p1.y + bvals[3]);
            *(float4*)r1 = make_float4(p2.x + bvals[4], p2.y + bvals[5],
                                       p3.x + bvals[6], p3.y + bvals[7]);
        }
    } else {
#pragma unroll
        for (int i = 0; i < 8; i++) {
            float* crow = C + (size_t)(bm + 8 * ty + i) * N;
            float2 p0 = unpack2(acc[i][0]), p1 = unpack2(acc[i][1]);
            float2 p2 = unpack2(acc[i][2]), p3 = unpack2(acc[i][3]);
            *(float4*)(crow + g0) = make_float4(p0.x + bvals[0], p0.y + bvals[1],
                                                p1.x + bvals[2], p1.y + bvals[3]);
            *(float4*)(crow + g1) = make_float4(p2.x + bvals[4], p2.y + bvals[5],
                                                p3.x + bvals[6], p3.y + bvals[7]);
        }
    }
}

// ---------------- accurate cos for x in [0, ~6500], fast-math-proof ----------------
__device__ __forceinline__ float cos_cw(float x) {
    float k = rintf(x * 0.31830988618379067f);
    float r = fmaf(-k, 3.14159274101257324f, x);
    r = fmaf(-k, -8.74227765734758e-8f, r);
    float r2 = r * r;
    float p = -2.75573192e-7f;
    p = fmaf(p, r2, 2.48015873e-5f);
    p = fmaf(p, r2, -1.38888889e-3f);
    p = fmaf(p, r2, 4.16666667e-2f);
    p = fmaf(p, r2, -0.5f);
    p = fmaf(p, r2, 1.0f);
    int ki = (int)k;
    return (ki & 1) ? -p : p;
}

// ---------------- per-head mask weight table ----------------
__global__ void mask_table_kernel(const float* __restrict__ sp, const float* __restrict__ pw,
                                  const float* __restrict__ rw) {
    const int h = blockIdx.x;
    float span = 2048.0f / (1.0f + expf(-sp[h]));
    float period = 2.0f + 2.0f / (1.0f + expf(-pw[h]));
    float amp = period * 0.25f;
    float ratio = -0.25f + 0.5f / (1.0f + expf(-rw[h]));
    float offset = period * ratio;
    for (int rel = threadIdx.x; rel < T_; rel += blockDim.x) {
        float relf = (float)rel;
        float mp = ((32.0f - relf) + span) * 0.03125f;
        mp = fminf(fmaxf(mp, 0.0f), 1.0f);
        float arg = __fdiv_rn(__fmul_rn(6.2831855f, relf), period);
        float wave = (0.5f * (cos_cw(arg) + 1.0f)) * amp + 0.5f + offset;
        wave = fminf(fmaxf(wave, 0.0f), 1.0f);
        g_W[h * T_ + rel] = mp * wave;
    }
}

// ---------------- fused masked flash attention (R6-proven) ----------------
__global__ __launch_bounds__(256)
void flash_kernel(const float* __restrict__ sp, float* __restrict__ y) {
    extern __shared__ float smf[];
    float* Qs = smf;
    float* Ks = smf + 64 * 132;
    float* Vs = smf + 64 * 132 + 64 * 68;
    float* Ps = smf + 64 * 132 + 2 * 64 * 68;

    const int iTile = (int)gridDim.x - 1 - (int)blockIdx.x;
    const int h = blockIdx.y, b = blockIdx.z;
    const int tid = threadIdx.x, tx = tid & 15, ty = tid >> 4;
    const int i0 = iTile * 128;

    float span = 2048.0f / (1.0f + expf(-sp[h]));
    float cutoff = span + 32.0f;
    const float* Wt = g_W + h * T_;

    const float* qg = g_q + ((size_t)(b * H_ + h) * T_ + i0) * D_;
    const float* kgBase = g_k + (size_t)(b * H_ + h) * T_ * D_;
    const float* vgBase = g_v + (size_t)(b * H_ + h) * T_ * D_;

    const int ldr = tid >> 4;
    const int ldd = (tid & 15) << 2;

#pragma unroll
    for (int rep = 0; rep < 8; rep++) {
        int r = rep * 16 + ldr;
        float4 qv = *(const float4*)&qg[r * 64 + ldd];
        Qs[(ldd + 0) * 132 + (r ^ sw4(ldd + 0))] = qv.x;
        Qs[(ldd + 1) * 132 + (r ^ sw4(ldd + 1))] = qv.y;
        Qs[(ldd + 2) * 132 + (r ^ sw4(ldd + 2))] = qv.z;
        Qs[(ldd + 3) * 132 + (r ^ sw4(ldd + 3))] = qv.w;
    }

    float m_i[8], l_i[8];
    ull O2[8][2];
#pragma unroll
    for (int r = 0; r < 8; r++) {
        m_i[r] = -1e30f; l_i[r] = 0.0f;
        O2[r][0] = 0ull; O2[r][1] = 0ull;
    }

    int v0 = i0 - (int)cutoff - 63;
    int jStart = (v0 > 0) ? (v0 >> 6) : 0;
    const int jEnd = (i0 + 127) >> 6;

    float4 kreg[4], vreg[4];
    {
        const int j0 = jStart * 64;
#pragma unroll
        for (int rep = 0; rep < 4; rep++) {
            int r = rep * 16 + ldr;
            kreg[rep] = *(const float4*)&kgBase[(size_t)(j0 + r) * 64 + ldd];
            vreg[rep] = *(const float4*)&vgBase[(size_t)(j0 + r) * 64 + ldd];
        }
    }

    for (int jt = jStart; jt <= jEnd; jt++) {
        const int j0 = jt * 64;
        __syncthreads();
#pragma unroll
        for (int rep = 0; rep < 4; rep++) {
            int r = rep * 16 + ldr;
            Ks[(ldd + 0) * 68 + (r ^ sw4(ldd + 0))] = kreg[rep].x;
            Ks[(ldd + 1) * 68 + (r ^ sw4(ldd + 1))] = kreg[rep].y;
            Ks[(ldd + 2) * 68 + (r ^ sw4(ldd + 2))] = kreg[rep].z;
            Ks[(ldd + 3) * 68 + (r ^ sw4(ldd + 3))] = kreg[rep].w;
            *(float4*)&Vs[r * 68 + ldd] = vreg[rep];
        }
        __syncthreads();

        if (jt < jEnd) {
            const int jn = j0 + 64;
#pragma unroll
            for (int rep = 0; rep < 4; rep++) {
                int r = rep * 16 + ldr;
                kreg[rep] = *(const float4*)&kgBase[(size_t)(jn + r) * 64 + ldd];
                vreg[rep] = *(const float4*)&vgBase[(size_t)(jn + r) * 64 + ldd];
            }
        }

        ull s2[8][2];
#pragma unroll
        for (int r = 0; r < 8; r++) { s2[r][0] = 0ull; s2[r][1] = 0ull; }
#pragma unroll 4
        for (int d = 0; d < 64; d++) {
            const int sw = sw4(d);
            float a[8];
            *(float4*)&a[0] = *(const float4*)&Qs[d * 132 + ((8 * ty) ^ sw)];
            *(float4*)&a[4] = *(const float4*)&Qs[d * 132 + ((8 * ty + 4) ^ sw)];
            ulonglong2 kp = *(const ulonglong2*)&Ks[d * 68 + ((4 * tx) ^ sw)];
#pragma unroll
            for (int r = 0; r < 8; r++) {
                ull aa = dup2(a[r]);
                fma2(s2[r][0], aa, kp.x);
                fma2(s2[r][1], aa, kp.y);
            }
        }

        float p[8][4], mloc[8];
#pragma unroll
        for (int r = 0; r < 8; r++) {
            float2 u0 = unpack2(s2[r][0]), u1 = unpack2(s2[r][1]);
            float s[4] = {u0.x, u0.y, u1.x, u1.y};
            int ig = i0 + 8 * ty + r;
            mloc[r] = -1e30f;
#pragma unroll
            for (int c = 0; c < 4; c++) {
                int jg = j0 + 4 * tx + c;
                int reli = ig - jg;
                if (reli < 0) {
                    s[c] = -1e30f; p[r][c] = 0.0f;
                } else {
                    float sv = s[c] * 0.125f;
                    s[c] = sv;
                    p[r][c] = __ldg(&Wt[reli]);
                    mloc[r] = fmaxf(mloc[r], sv);
                }
            }
            s2[r][0] = (ull)__float_as_uint(s[0]) | ((ull)__float_as_uint(s[1]) << 32);
            s2[r][1] = (ull)__float_as_uint(s[2]) | ((ull)__float_as_uint(s[3]) << 32);
        }
#pragma unroll
        for (int off = 1; off < 16; off <<= 1)
#pragma unroll
            for (int r = 0; r < 8; r++)
                mloc[r] = fmaxf(mloc[r], __shfl_xor_sync(0xffffffffu, mloc[r], off));

        float lloc[8], alpha[8];
#pragma unroll
        for (int r = 0; r < 8; r++) {
            float mn = fmaxf(m_i[r], mloc[r]);
            alpha[r] = __expf(m_i[r] - mn);
            m_i[r] = mn;
            float2 u0 = unpack2(s2[r][0]), u1 = unpack2(s2[r][1]);
            float s[4] = {u0.x, u0.y, u1.x, u1.y};
            lloc[r] = 0.0f;
#pragma unroll
            for (int c = 0; c < 4; c++) {
                p[r][c] *= __expf(s[c] - mn);
                lloc[r] += p[r][c];
            }
        }
#pragma unroll
        for (int off = 1; off < 16; off <<= 1)
#pragma unroll
            for (int r = 0; r < 8; r++)
                lloc[r] += __shfl_xor_sync(0xffffffffu, lloc[r], off);
#pragma unroll
        for (int r = 0; r < 8; r++) {
            l_i[r] = l_i[r] * alpha[r] + lloc[r];
            ull aa = dup2(alpha[r]);
            mul2(O2[r][0], O2[r][0], aa);
            mul2(O2[r][1], O2[r][1], aa);
        }

#pragma unroll
        for (int c = 0; c < 4; c++) {
            const int jj = 4 * tx + c;
            const int sw = sw4(jj);
#pragma unroll
            for (int r = 0; r < 8; r++)
                Ps[jj * 132 + ((8 * ty + r) ^ sw)] = p[r][c];
        }
        __syncthreads();

#pragma unroll 4
        for (int j = 0; j < 64; j++) {
            const int sw = sw4(j);
            float a[8];
            *(float4*)&a[0] = *(const float4*)&Ps[j * 132 + ((8 * ty) ^ sw)];
            *(float4*)&a[4] = *(const float4*)&Ps[j * 132 + ((8 * ty + 4) ^ sw)];
            ulonglong2 vp = *(const ulonglong2*)&Vs[j * 68 + 4 * tx];
#pragma unroll
            for (int r = 0; r < 8; r++) {
                ull aa = dup2(a[r]);
                fma2(O2[r][0], aa, vp.x);
                fma2(O2[r][1], aa, vp.y);
            }
        }
    }

#pragma unroll
    for (int r = 0; r < 8; r++) {
        int ig = i0 + 8 * ty + r;
        float inv = 1.0f / l_i[r];
        float2 o0 = unpack2(O2[r][0]), o1 = unpack2(O2[r][1]);
        float4 outv = make_float4(o0.x * inv, o0.y * inv, o1.x * inv, o1.y * inv);
        *(float4*)&y[(size_t)(b * T_ + ig) * C_ + h * D_ + 4 * tx] = outv;
    }
}

// ---------------- span loss (scalar) ----------------
__global__ void span_loss_kernel(const float* __restrict__ sp, const float* __restrict__ pw,
                                 const float* __restrict__ rw, float* __restrict__ out) {
    int hh = threadIdx.x;
    float val = 0.0f;
    if (hh < H_) {
        float span = 2048.0f / (1.0f + expf(-sp[hh]));
        float period = 2.0f + 2.0f / (1.0f + expf(-pw[hh]));
        float ratio = -0.25f + 0.5f / (1.0f + expf(-rw[hh]));
        float lt = 1.0f / period + 2.0f * ratio - 0.25f + 0.5f;
        val = (span + 32.0f) * lt;
    }
#pragma unroll
    for (int off = 16; off > 0; off >>= 1)
        val += __shfl_xor_sync(0xffffffffu, val, off);
    if (hh == 0) out[0] = 2e-6f * val / 16.0f;
}

// ---------------- launch ----------------
extern "C" void kernel_launch(void* const* d_in, const int* in_sizes, int n_in,
                              void* d_out, int out_size) {
    (void)in_sizes; (void)n_in;
    const float* x      = (const float*)d_in[0];
    const float* w_attn = (const float*)d_in[1];
    const float* b_attn = (const float*)d_in[2];
    const float* w_proj = (const float*)d_in[3];
    const float* b_proj = (const float*)d_in[4];
    const float* sp     = (const float*)d_in[5];
    const float* pw     = (const float*)d_in[6];
    const float* rw     = (const float*)d_in[7];
    float* out = (float*)d_out;

    float* y_ptr;
    cudaGetSymbolAddress((void**)&y_ptr, g_y);
    __nv_bfloat16 *xhi, *xlo, *yhi, *ylo, *wahiT, *waloT, *wphiT, *wploT;
    cudaGetSymbolAddress((void**)&xhi, g_xhi);
    cudaGetSymbolAddress((void**)&xlo, g_xlo);
    cudaGetSymbolAddress((void**)&yhi, g_yhi);
    cudaGetSymbolAddress((void**)&ylo, g_ylo);
    cudaGetSymbolAddress((void**)&wahiT, g_wahiT);
    cudaGetSymbolAddress((void**)&waloT, g_waloT);
    cudaGetSymbolAddress((void**)&wphiT, g_wphiT);
    cudaGetSymbolAddress((void**)&wploT, g_wploT);

    const int MMA_SMEM = 4 * 128 * LDS_ * 2;   // 73,728 B
    cudaFuncSetAttribute(mma_gemm_kernel<true>,  cudaFuncAttributeMaxDynamicSharedMemorySize, MMA_SMEM);
    cudaFuncSetAttribute(mma_gemm_kernel<false>, cudaFuncAttributeMaxDynamicSharedMemorySize, MMA_SMEM);

    reset_flags_kernel<<<1, 1>>>();
    // mask table + input conversions
    mask_table_kernel<<<H_, 256>>>(sp, pw, rw);
    split_kernel<<<4096, 256>>>(x, xhi, xlo);
    splitT_kernel<<<dim3(96, 32), 256>>>(w_attn, wahiT, waloT, 3072);
    splitT_kernel<<<dim3(32, 32), 256>>>(w_proj, wphiT, wploT, 1024);
    // qkv GEMM on tensor cores (mma.sync) -> verify -> SIMT fallback (no-op when OK)
    mma_gemm_kernel<true><<<dim3(24, 32), 256, MMA_SMEM>>>(b_attn, nullptr);
    check_kernel<true><<<4, 256>>>(x, w_attn, b_attn, nullptr);
    fb_gemm_kernel<true><<<dim3(24, 32), 256>>>(x, w_attn, b_attn, nullptr, 4096, 3072, 1024);
    // fused masked attention (Br=128, Bc=64)
    const size_t FSM = (size_t)(64 * 132 + 2 * 64 * 68 + 64 * 132) * sizeof(float);
    cudaFuncSetAttribute(flash_kernel, cudaFuncAttributeMaxDynamicSharedMemorySize, (int)FSM);
    flash_kernel<<<dim3(16, 16, 2), 256, FSM>>>(sp, y_ptr);
    // proj GEMM on tensor cores -> verify -> SIMT fallback
    split_kernel<<<4096, 256>>>(y_ptr, yhi, ylo);
    mma_gemm_kernel<false><<<dim3(8, 32), 256, MMA_SMEM>>>(b_proj, out);
    check_kernel<false><<<4, 256>>>(y_ptr, w_proj, b_proj, out);
    fb_gemm_kernel<false><<<dim3(8, 32), 256>>>(y_ptr, w_proj, b_proj, out, 4096, 1024, 1024);
    // span loss -> last output element
    span_loss_kernel<<<1, 32>>>(sp, pw, rw, out + (size_t)out_size - 1);
}